// round 11
// baseline (speedup 1.0000x reference)
#include <cuda_runtime.h>
#include <cuda_fp16.h>

// ===================== problem constants =====================
#define KDIM    256            // c*64+d
#define NDIM    512            // t*32+o
#define MTILE   128
#define NTILE   256            // per-CTA N half
#define THREADS 512
#define KC      64             // K chunk
#define NCHUNK  4
#define BATCH   32768

// ===================== device scratch =====================
__device__ __half g_w2h[NDIM * KDIM];      // fused W2 = Wm x Wg, fp16
__device__ __half g_xh[BATCH * KDIM];      // x pre-converted to fp16 (16 MB)
__device__ float  g_beff[NDIM];

// ===================== smem layout =====================
#define PITCH   144                        // 64 fp16 (128B) + 16B pad (validated conflict-free)
#define BPLANE  (NTILE * PITCH)            // 36864 per K-chunk plane of B
#define ACH     (MTILE * PITCH)            // 18432 per A chunk buffer
#define SM_B    0                          // 4 planes resident: 147456
#define SM_A    (4 * BPLANE)               // 4 buffers: 73728
#define SM_BEFF (SM_A + 4 * ACH)           // 221184
#define SMEM_TOTAL (SM_BEFF + NTILE * 4)   // 222208 (< 227 KB)

// ===================== PTX helpers (validated mappings) =====================
__device__ __forceinline__ unsigned smem_u32(const void* p) {
    unsigned a;
    asm("{ .reg .u64 t; cvta.to.shared.u64 t, %1; cvt.u32.u64 %0, t; }" : "=r"(a) : "l"(p));
    return a;
}
__device__ __forceinline__ void ldmx4(unsigned* r, unsigned addr) {
    asm volatile("ldmatrix.sync.aligned.m8n8.x4.shared.b16 {%0,%1,%2,%3}, [%4];"
                 : "=r"(r[0]), "=r"(r[1]), "=r"(r[2]), "=r"(r[3]) : "r"(addr));
}
__device__ __forceinline__ void mma16816(float* d, const unsigned* a, const unsigned* b) {
    asm volatile("mma.sync.aligned.m16n8k16.row.col.f32.f16.f16.f32 "
                 "{%0,%1,%2,%3}, {%4,%5,%6,%7}, {%8,%9}, {%0,%1,%2,%3};"
                 : "+f"(d[0]), "+f"(d[1]), "+f"(d[2]), "+f"(d[3])
                 : "r"(a[0]), "r"(a[1]), "r"(a[2]), "r"(a[3]), "r"(b[0]), "r"(b[1]));
}
__device__ __forceinline__ void stcs2(float* p, float a, float b) {
    asm volatile("st.global.cs.v2.f32 [%0], {%1, %2};" :: "l"(p), "f"(a), "f"(b) : "memory");
}
__device__ __forceinline__ void cp_async16(unsigned dst, const void* src) {
    asm volatile("cp.async.ca.shared.global [%0], [%1], 16;"
                 :: "r"(dst), "l"(__cvta_generic_to_global(src)) : "memory");
}
#define CP_COMMIT()  asm volatile("cp.async.commit_group;" ::: "memory")
#define CP_WAIT2()   asm volatile("cp.async.wait_group 2;" ::: "memory")

// ===================== prep 1: fused W2 fp16 + effective bias =====================
__global__ void prep_w(const float* __restrict__ Wg, const float* __restrict__ bg,
                       const float* __restrict__ Wm) {
    int e = blockIdx.x * blockDim.x + threadIdx.x;
    if (e < NDIM * KDIM) {
        int n = e >> 8, k = e & 255;
        int t = n >> 5, o = n & 31;
        int c = k >> 6, d = k & 63;
        g_w2h[e] = __float2half_rn(Wm[t * 4 + c] * Wg[(t * 32 + o) * 64 + d]);
    }
    if (e < NDIM) {
        int t = e >> 5;
        float s = Wm[t * 4] + Wm[t * 4 + 1] + Wm[t * 4 + 2] + Wm[t * 4 + 3];
        g_beff[e] = s * bg[e];
    }
}

// ===================== prep 2: x fp32 -> fp16 (streaming) =====================
__global__ __launch_bounds__(512, 2) void prep_x(const float* __restrict__ x) {
    int id = blockIdx.x * 512 + threadIdx.x;      // 1,048,576 threads, 8 floats each
    const float4* s = (const float4*)(x) + id * 2;
    float4 v0 = s[0], v1 = s[1];
    __half2 h0 = __float22half2_rn(make_float2(v0.x, v0.y));
    __half2 h1 = __float22half2_rn(make_float2(v0.z, v0.w));
    __half2 h2 = __float22half2_rn(make_float2(v1.x, v1.y));
    __half2 h3 = __float22half2_rn(make_float2(v1.z, v1.w));
    ((uint4*)g_xh)[id] = make_uint4(*(unsigned*)&h0, *(unsigned*)&h1,
                                    *(unsigned*)&h2, *(unsigned*)&h3);
}

// ===================== persistent fused GEMM: out = relu(Xh @ W2h^T + beff) ==========
__global__ __launch_bounds__(THREADS, 1)
void gemm_kernel(float* __restrict__ out, int ntm, int mstride) {
    extern __shared__ char smem[];
    const unsigned sb = smem_u32(smem);
    const int tid = threadIdx.x, wid = tid >> 5, l = tid & 31;
    const int ntl = blockIdx.x & 1;           // fixed N half per CTA
    int       mt  = blockIdx.x >> 1;          // starting M tile
    const int wm  = wid & 3;                  // 32 rows per warp
    const int wn  = wid >> 2;                 // 64 cols per warp

    // ---- one-time: stage resident B (fp16, 4 K-chunk planes) + beff ----
    #pragma unroll
    for (int i = 0; i < 16; i++) {
        int u = tid + i * THREADS;            // 8192 uint4: n(256) x kc(4) x j(8)
        int n = u >> 5, r = u & 31;
        int kc = r >> 3, j = r & 7;
        size_t src = ((size_t)(ntl * NTILE + n)) * (KDIM / 8) + kc * 8 + j;
        unsigned off = (unsigned)(kc * BPLANE + n * PITCH + j * 16);
        *(uint4*)(smem + SM_B + off) = ((const uint4*)g_w2h)[src];
    }
    if (tid < NTILE) ((float*)(smem + SM_BEFF))[tid] = g_beff[ntl * NTILE + tid];

    // cp.async issue of one A chunk (mt tile, K chunk kc) into buffer b
    auto issue = [&](int imt, int ikc, int b) {
        #pragma unroll
        for (int i = 0; i < 2; i++) {
            int id = tid + i * THREADS;       // 1024 x 16B segments
            int m = id >> 3, j = id & 7;
            unsigned dst = sb + SM_A + (unsigned)(b * ACH + m * PITCH + j * 16);
            const __half* src = g_xh + ((size_t)(imt * MTILE + m)) * KDIM + ikc * KC + j * 8;
            cp_async16(dst, src);
        }
    };

    // ---- prologue: 3 chunks in flight ----
    if (mt < ntm) { issue(mt, 0, 0); } CP_COMMIT();
    if (mt < ntm) { issue(mt, 1, 1); } CP_COMMIT();
    if (mt < ntm) { issue(mt, 2, 2); } CP_COMMIT();

    const unsigned a_lane = sb + SM_A +
        (unsigned)((wm * 32 + (l & 15)) * PITCH + (l >> 4) * 16);
    const unsigned b_lane = sb + SM_B +
        (unsigned)((wn * 64 + (l & 7) + ((l >> 4) & 1) * 8) * PITCH +
                   ((l >> 3) & 1) * 16);
    const float* beffs = (const float*)(smem + SM_BEFF);

    __syncthreads();  // B + beff visible

    int buf = 0;
    while (mt < ntm) {
        float acc[2][8][4];
        #pragma unroll
        for (int i = 0; i < 2; i++)
            #pragma unroll
            for (int j = 0; j < 8; j++)
                #pragma unroll
                for (int q = 0; q < 4; q++) acc[i][j][q] = 0.f;

        #pragma unroll 1
        for (int kc = 0; kc < NCHUNK; kc++) {
            CP_WAIT2();          // chunk (this one) landed >=3 commits ago
            __syncthreads();     // visible to all warps; also guards buffer reuse

            // ---- issue chunk kc+3 (next tile wraps) ----
            {
                int ikc = kc + 3, imt = mt;
                if (ikc >= NCHUNK) { ikc -= NCHUNK; imt = mt + mstride; }
                if (imt < ntm) issue(imt, ikc, (buf + 3) & 3);
                CP_COMMIT();
            }

            // ---- compute: 4 k16-steps vs resident B plane kc ----
            const unsigned ab = a_lane + (unsigned)(buf * ACH);
            const unsigned bb = b_lane + (unsigned)(kc * BPLANE);
            #pragma unroll
            for (int ks = 0; ks < 4; ks++) {
                unsigned bh[4][4];
                #pragma unroll
                for (int jj = 0; jj < 4; jj++)
                    ldmx4(bh[jj], bb + (unsigned)(jj * 16 * PITCH + ks * 32));
                #pragma unroll
                for (int mb = 0; mb < 2; mb++) {
                    unsigned ah[4];
                    ldmx4(ah, ab + (unsigned)(mb * 16 * PITCH + ks * 32));
                    #pragma unroll
                    for (int jj = 0; jj < 4; jj++) {
                        mma16816(acc[mb][jj * 2],     ah, bh[jj]);
                        mma16816(acc[mb][jj * 2 + 1], ah, bh[jj] + 2);
                    }
                }
            }
            buf = (buf + 1) & 3;
        }

        // ---- epilogue: bias + relu, streaming stores ----
        #pragma unroll
        for (int mb = 0; mb < 2; mb++) {
            const int r0 = mt * MTILE + wm * 32 + mb * 16 + (l >> 2);
            #pragma unroll
            for (int j = 0; j < 8; j++) {
                int n = wn * 64 + j * 8 + 2 * (l & 3);
                float2 bv = *(const float2*)(beffs + n);
                float* p0 = out + (size_t)r0 * NDIM + ntl * NTILE + n;
                stcs2(p0,
                      fmaxf(acc[mb][j][0] + bv.x, 0.f),
                      fmaxf(acc[mb][j][1] + bv.y, 0.f));
                stcs2(p0 + 8 * NDIM,
                      fmaxf(acc[mb][j][2] + bv.x, 0.f),
                      fmaxf(acc[mb][j][3] + bv.y, 0.f));
            }
        }
        mt += mstride;
    }
}

// ===================== launch =====================
extern "C" void kernel_launch(void* const* d_in, const int* in_sizes, int n_in,
                              void* d_out, int out_size) {
    const float* x  = (const float*)d_in[0];
    const float* Wg = (const float*)d_in[1];
    const float* bg = (const float*)d_in[2];
    const float* Wm = (const float*)d_in[3];
    float* out = (float*)d_out;

    const int B   = in_sizes[0] / KDIM;      // 32768
    const int ntm = B / MTILE;               // 256

    prep_w<<<(NDIM * KDIM + 255) / 256, 256>>>(Wg, bg, Wm);
    prep_x<<<(B * KDIM / 8 + 511) / 512, 512>>>(x);

    cudaFuncSetAttribute(gemm_kernel,
                         cudaFuncAttributeMaxDynamicSharedMemorySize, SMEM_TOTAL);

    int dev = 0, sms = 148;
    cudaGetDevice(&dev);
    cudaDeviceGetAttribute(&sms, cudaDevAttrMultiProcessorCount, dev);
    int grid = sms & ~1;                     // even: half the CTAs per N half
    if (grid < 2) grid = 2;
    if (grid > 2 * ntm) grid = 2 * ntm;
    int mstride = grid >> 1;

    gemm_kernel<<<grid, THREADS, SMEM_TOTAL>>>(out, ntm, mstride);
}

// round 12
// speedup vs baseline: 1.1474x; 1.1474x over previous
#include <cuda_runtime.h>
#include <cuda_fp16.h>

// ===================== problem constants =====================
#define KDIM    256            // c*64+d
#define NDIM    512            // t*32+o
#define MTILE   64
#define NTILE   128            // per-CTA N quarter
#define THREADS 256
#define KC      64             // K chunk (== one channel c)
#define NCHUNK  4

// ===================== smem layout =====================
#define PITCH   144                        // 64 fp16 (128B) + 16B pad (validated conflict-free)
#define BPLANE  (NTILE * PITCH)            // 18432 per K-chunk plane of B
#define ACH     (MTILE * PITCH)            // 9216 per A chunk buffer
#define SM_B    0                          // 4 planes resident: 73728
#define SM_A    (4 * BPLANE)               // 2 buffers: 18432
#define SM_BEFF (SM_A + 2 * ACH)           // 92160
#define SMEM_TOTAL (SM_BEFF + NTILE * 4)   // 92672 (x2 CTA = 185344 < 227KB)

// ===================== PTX helpers (validated mappings) =====================
__device__ __forceinline__ unsigned smem_u32(const void* p) {
    unsigned a;
    asm("{ .reg .u64 t; cvta.to.shared.u64 t, %1; cvt.u32.u64 %0, t; }" : "=r"(a) : "l"(p));
    return a;
}
__device__ __forceinline__ void ldmx4(unsigned* r, unsigned addr) {
    asm volatile("ldmatrix.sync.aligned.m8n8.x4.shared.b16 {%0,%1,%2,%3}, [%4];"
                 : "=r"(r[0]), "=r"(r[1]), "=r"(r[2]), "=r"(r[3]) : "r"(addr));
}
__device__ __forceinline__ void mma16816(float* d, const unsigned* a, const unsigned* b) {
    asm volatile("mma.sync.aligned.m16n8k16.row.col.f32.f16.f16.f32 "
                 "{%0,%1,%2,%3}, {%4,%5,%6,%7}, {%8,%9}, {%0,%1,%2,%3};"
                 : "+f"(d[0]), "+f"(d[1]), "+f"(d[2]), "+f"(d[3])
                 : "r"(a[0]), "r"(a[1]), "r"(a[2]), "r"(a[3]), "r"(b[0]), "r"(b[1]));
}
__device__ __forceinline__ void stcs2(float* p, float a, float b) {
    asm volatile("st.global.cs.v2.f32 [%0], {%1, %2};" :: "l"(p), "f"(a), "f"(b) : "memory");
}

// ===================== single fused kernel: out = relu(Xh @ (Wm*Wg)h^T + beff) =========
__global__ __launch_bounds__(THREADS, 2)
void gemm_kernel(const float* __restrict__ x,   float* __restrict__ out,
                 const float* __restrict__ Wg,  const float* __restrict__ bg,
                 const float* __restrict__ Wm,  int ntm, int mstride) {
    extern __shared__ char smem[];
    const unsigned sb = smem_u32(smem);
    const int tid = threadIdx.x, wid = tid >> 5, l = tid & 31;
    const int ntl = blockIdx.x & 3;           // fixed N quarter per CTA
    int       mt  = blockIdx.x >> 2;          // starting M tile
    const int wm  = wid & 1;                  // 32 rows per warp
    const int wn  = wid >> 1;                 // 32 cols per warp

    // ---- prologue LDG: x chunk 0 of first tile into regs (hides under staging) ----
    float4 xr[4];
    if (mt < ntm) {
        #pragma unroll
        for (int i = 0; i < 4; i++) {
            int f4 = tid + i * THREADS;       // 1024 float4: m(64) x k4(16)
            int m = f4 >> 4, k4 = f4 & 15;
            xr[i] = *(const float4*)(x + ((size_t)(mt * MTILE + m)) * KDIM + k4 * 4);
        }
    }

    // ---- one-time: stage B with INLINE weight fusion (W2 = Wm[t,kc] * Wg) ----
    // 8192 float4 elements: n(128) x kc(4) x j4(16);  c == kc
    #pragma unroll
    for (int i = 0; i < 32; i++) {
        int u = tid + i * THREADS;
        int n = u >> 6, r = u & 63;
        int kc = r >> 4, j4 = r & 15;
        int gn = ntl * NTILE + n;             // global n = t*32+o
        float wmv = Wm[(gn >> 5) * 4 + kc];
        float4 v = *(const float4*)(Wg + (size_t)gn * 64 + j4 * 4);
        __half2 h0 = __float22half2_rn(make_float2(v.x * wmv, v.y * wmv));
        __half2 h1 = __float22half2_rn(make_float2(v.z * wmv, v.w * wmv));
        *(uint2*)(smem + SM_B + kc * BPLANE + n * PITCH + j4 * 8) =
            make_uint2(*(unsigned*)&h0, *(unsigned*)&h1);
    }
    // beff = (sum_c Wm[t,c]) * bg[t,o]
    if (tid < NTILE) {
        int gn = ntl * NTILE + tid;
        int t = gn >> 5;
        float s = Wm[t * 4] + Wm[t * 4 + 1] + Wm[t * 4 + 2] + Wm[t * 4 + 3];
        ((float*)(smem + SM_BEFF))[tid] = s * bg[gn];
    }

    const unsigned a_lane = sb + SM_A +
        (unsigned)((wm * 32 + (l & 15)) * PITCH + (l >> 4) * 16);
    const unsigned b_lane = sb + SM_B +
        (unsigned)((wn * 32 + (l & 7) + ((l >> 4) & 1) * 8) * PITCH +
                   ((l >> 3) & 1) * 16);
    const float* beffs = (const float*)(smem + SM_BEFF);

    __syncthreads();  // B + beff visible

    int buf = 0;
    while (mt < ntm) {
        float acc[2][4][4];
        #pragma unroll
        for (int i = 0; i < 2; i++)
            #pragma unroll
            for (int j = 0; j < 4; j++)
                #pragma unroll
                for (int q = 0; q < 4; q++) acc[i][j][q] = 0.f;

        #pragma unroll 1
        for (int kc = 0; kc < NCHUNK; kc++) {
            // ---- STS: regs -> A[buf] as fp16 ----
            #pragma unroll
            for (int i = 0; i < 4; i++) {
                int f4 = tid + i * THREADS;
                int m = f4 >> 4, k4 = f4 & 15;
                float4 v = xr[i];
                __half2 h0 = __float22half2_rn(make_float2(v.x, v.y));
                __half2 h1 = __float22half2_rn(make_float2(v.z, v.w));
                *(uint2*)(smem + SM_A + buf * ACH + m * PITCH + k4 * 8) =
                    make_uint2(*(unsigned*)&h0, *(unsigned*)&h1);
            }
            __syncthreads();

            // ---- LDG next chunk (hides under compute) ----
            int nkc = kc + 1, nmt = mt;
            if (nkc == NCHUNK) { nkc = 0; nmt = mt + mstride; }
            if (nmt < ntm) {
                #pragma unroll
                for (int i = 0; i < 4; i++) {
                    int f4 = tid + i * THREADS;
                    int m = f4 >> 4, k4 = f4 & 15;
                    xr[i] = *(const float4*)(x + ((size_t)(nmt * MTILE + m)) * KDIM
                                             + nkc * KC + k4 * 4);
                }
            }

            // ---- compute: 4 k16-steps vs resident B plane kc ----
            const unsigned ab = a_lane + (unsigned)(buf * ACH);
            const unsigned bb = b_lane + (unsigned)(kc * BPLANE);
            #pragma unroll
            for (int ks = 0; ks < 4; ks++) {
                unsigned bh[2][4];
                ldmx4(bh[0], bb + (unsigned)(ks * 32));
                ldmx4(bh[1], bb + (unsigned)(16 * PITCH + ks * 32));
                #pragma unroll
                for (int mb = 0; mb < 2; mb++) {
                    unsigned ah[4];
                    ldmx4(ah, ab + (unsigned)(mb * 16 * PITCH + ks * 32));
                    #pragma unroll
                    for (int jj = 0; jj < 2; jj++) {
                        mma16816(acc[mb][jj * 2],     ah, bh[jj]);      // n8 tile 2jj
                        mma16816(acc[mb][jj * 2 + 1], ah, bh[jj] + 2);  // n8 tile 2jj+1
                    }
                }
            }
            buf ^= 1;
        }

        // ---- epilogue: bias + relu, streaming stores ----
        #pragma unroll
        for (int mb = 0; mb < 2; mb++) {
            const int r0 = mt * MTILE + wm * 32 + mb * 16 + (l >> 2);
            #pragma unroll
            for (int j = 0; j < 4; j++) {
                int n = wn * 32 + j * 8 + 2 * (l & 3);
                float2 bv = *(const float2*)(beffs + n);
                float* p0 = out + (size_t)r0 * NDIM + ntl * NTILE + n;
                stcs2(p0,
                      fmaxf(acc[mb][j][0] + bv.x, 0.f),
                      fmaxf(acc[mb][j][1] + bv.y, 0.f));
                stcs2(p0 + 8 * NDIM,
                      fmaxf(acc[mb][j][2] + bv.x, 0.f),
                      fmaxf(acc[mb][j][3] + bv.y, 0.f));
            }
        }
        mt += mstride;
    }
}

// ===================== launch =====================
extern "C" void kernel_launch(void* const* d_in, const int* in_sizes, int n_in,
                              void* d_out, int out_size) {
    const float* x  = (const float*)d_in[0];
    const float* Wg = (const float*)d_in[1];
    const float* bg = (const float*)d_in[2];
    const float* Wm = (const float*)d_in[3];
    float* out = (float*)d_out;

    const int B   = in_sizes[0] / KDIM;      // 32768
    const int ntm = B / MTILE;               // 512

    cudaFuncSetAttribute(gemm_kernel,
                         cudaFuncAttributeMaxDynamicSharedMemorySize, SMEM_TOTAL);

    int dev = 0, sms = 148;
    cudaGetDevice(&dev);
    cudaDeviceGetAttribute(&sms, cudaDevAttrMultiProcessorCount, dev);
    int grid = (2 * sms) & ~3;               // 2 CTAs/SM, multiple of 4 (N quarters)
    if (grid < 4) grid = 4;
    if (grid > 4 * ntm) grid = 4 * ntm;
    int mstride = grid >> 2;

    gemm_kernel<<<grid, THREADS, SMEM_TOTAL>>>(x, out, Wg, bg, Wm, ntm, mstride);
}

// round 13
// speedup vs baseline: 1.1608x; 1.0117x over previous
#include <cuda_runtime.h>
#include <cuda_fp16.h>

// ===================== problem constants =====================
#define KDIM    256            // c*64+d
#define NDIM    512            // t*32+o
#define MTILE   128
#define NTILE   128            // per-CTA N quarter
#define THREADS 256
#define KC      64             // K chunk (== one channel c)
#define NCHUNK  4

// ===================== smem layout =====================
#define PITCH   144                        // 64 fp16 (128B) + 16B pad (validated conflict-free)
#define BPLANE  (NTILE * PITCH)            // 18432 per K-chunk plane of B
#define ACH     (MTILE * PITCH)            // 18432 per A chunk buffer
#define SM_B    0                          // 4 planes resident: 73728
#define SM_A    (4 * BPLANE)               // 2 buffers: 36864
#define SM_BEFF (SM_A + 2 * ACH)           // 110592
#define SMEM_TOTAL (SM_BEFF + NTILE * 4)   // 111104 (x2 CTA = 222208 < 227KB)

// ===================== PTX helpers (validated mappings) =====================
__device__ __forceinline__ unsigned smem_u32(const void* p) {
    unsigned a;
    asm("{ .reg .u64 t; cvta.to.shared.u64 t, %1; cvt.u32.u64 %0, t; }" : "=r"(a) : "l"(p));
    return a;
}
__device__ __forceinline__ void ldmx4(unsigned* r, unsigned addr) {
    asm volatile("ldmatrix.sync.aligned.m8n8.x4.shared.b16 {%0,%1,%2,%3}, [%4];"
                 : "=r"(r[0]), "=r"(r[1]), "=r"(r[2]), "=r"(r[3]) : "r"(addr));
}
__device__ __forceinline__ void mma16816(float* d, const unsigned* a, const unsigned* b) {
    asm volatile("mma.sync.aligned.m16n8k16.row.col.f32.f16.f16.f32 "
                 "{%0,%1,%2,%3}, {%4,%5,%6,%7}, {%8,%9}, {%0,%1,%2,%3};"
                 : "+f"(d[0]), "+f"(d[1]), "+f"(d[2]), "+f"(d[3])
                 : "r"(a[0]), "r"(a[1]), "r"(a[2]), "r"(a[3]), "r"(b[0]), "r"(b[1]));
}
__device__ __forceinline__ void stcs2(float* p, float a, float b) {
    asm volatile("st.global.cs.v2.f32 [%0], {%1, %2};" :: "l"(p), "f"(a), "f"(b) : "memory");
}

// ===================== single fused kernel: out = relu(Xh @ (Wm*Wg)h^T + beff) =========
__global__ __launch_bounds__(THREADS, 2)
void gemm_kernel(const float* __restrict__ x,   float* __restrict__ out,
                 const float* __restrict__ Wg,  const float* __restrict__ bg,
                 const float* __restrict__ Wm,  int ntm, int mstride) {
    extern __shared__ char smem[];
    const unsigned sb = smem_u32(smem);
    const int tid = threadIdx.x, wid = tid >> 5, l = tid & 31;
    const int ntl = blockIdx.x & 3;           // fixed N quarter per CTA
    int       mt  = blockIdx.x >> 2;          // starting M tile
    const int wm  = wid & 3;                  // 32 rows per warp
    const int wn  = wid >> 2;                 // 64 cols per warp

    // ---- one-time: stage B with INLINE weight fusion (W2 = Wm[t,kc] * Wg), c == kc ----
    // 8192 float4: n(128) x kc(4) x j4(16)
    #pragma unroll
    for (int i = 0; i < 32; i++) {
        int u = tid + i * THREADS;
        int n = u >> 6, r = u & 63;
        int kc = r >> 4, j4 = r & 15;
        int gn = ntl * NTILE + n;             // global n = t*32+o
        float wmv = Wm[(gn >> 5) * 4 + kc];
        float4 v = *(const float4*)(Wg + (size_t)gn * 64 + j4 * 4);
        __half2 h0 = __float22half2_rn(make_float2(v.x * wmv, v.y * wmv));
        __half2 h1 = __float22half2_rn(make_float2(v.z * wmv, v.w * wmv));
        *(uint2*)(smem + SM_B + kc * BPLANE + n * PITCH + j4 * 8) =
            make_uint2(*(unsigned*)&h0, *(unsigned*)&h1);
    }
    // beff = (sum_c Wm[t,c]) * bg[t,o]
    if (tid < NTILE) {
        int gn = ntl * NTILE + tid;
        int t = gn >> 5;
        float s = Wm[t * 4] + Wm[t * 4 + 1] + Wm[t * 4 + 2] + Wm[t * 4 + 3];
        ((float*)(smem + SM_BEFF))[tid] = s * bg[gn];
    }

    // ---- prologue LDG: x chunk 0 of first tile into regs ----
    float4 xr[8];
    if (mt < ntm) {
        #pragma unroll
        for (int i = 0; i < 8; i++) {
            int f4 = tid + i * THREADS;       // 2048 float4: m(128) x k4(16)
            int m = f4 >> 4, k4 = f4 & 15;
            xr[i] = *(const float4*)(x + ((size_t)(mt * MTILE + m)) * KDIM + k4 * 4);
        }
    }

    const unsigned a_lane = sb + SM_A +
        (unsigned)((wm * 32 + (l & 15)) * PITCH + (l >> 4) * 16);
    const unsigned b_lane = sb + SM_B +
        (unsigned)((wn * 64 + (l & 7) + ((l >> 4) & 1) * 8) * PITCH +
                   ((l >> 3) & 1) * 16);
    const float* beffs = (const float*)(smem + SM_BEFF);

    __syncthreads();  // B + beff visible

    int buf = 0;
    while (mt < ntm) {
        float acc[2][8][4];
        #pragma unroll
        for (int i = 0; i < 2; i++)
            #pragma unroll
            for (int j = 0; j < 8; j++)
                #pragma unroll
                for (int q = 0; q < 4; q++) acc[i][j][q] = 0.f;

        #pragma unroll 1
        for (int kc = 0; kc < NCHUNK; kc++) {
            // ---- STS: regs -> A[buf] as fp16 ----
            #pragma unroll
            for (int i = 0; i < 8; i++) {
                int f4 = tid + i * THREADS;
                int m = f4 >> 4, k4 = f4 & 15;
                float4 v = xr[i];
                __half2 h0 = __float22half2_rn(make_float2(v.x, v.y));
                __half2 h1 = __float22half2_rn(make_float2(v.z, v.w));
                *(uint2*)(smem + SM_A + buf * ACH + m * PITCH + k4 * 8) =
                    make_uint2(*(unsigned*)&h0, *(unsigned*)&h1);
            }
            __syncthreads();

            // ---- LDG next chunk (hides under compute) ----
            int nkc = kc + 1, nmt = mt;
            if (nkc == NCHUNK) { nkc = 0; nmt = mt + mstride; }
            if (nmt < ntm) {
                #pragma unroll
                for (int i = 0; i < 8; i++) {
                    int f4 = tid + i * THREADS;
                    int m = f4 >> 4, k4 = f4 & 15;
                    xr[i] = *(const float4*)(x + ((size_t)(nmt * MTILE + m)) * KDIM
                                             + nkc * KC + k4 * 4);
                }
            }

            // ---- compute: 4 k16-steps vs resident B plane kc (warp tile 32x64) ----
            const unsigned ab = a_lane + (unsigned)(buf * ACH);
            const unsigned bb = b_lane + (unsigned)(kc * BPLANE);
            #pragma unroll
            for (int ks = 0; ks < 4; ks++) {
                unsigned bh[4][4];
                #pragma unroll
                for (int jj = 0; jj < 4; jj++)
                    ldmx4(bh[jj], bb + (unsigned)(jj * 16 * PITCH + ks * 32));
                #pragma unroll
                for (int mb = 0; mb < 2; mb++) {
                    unsigned ah[4];
                    ldmx4(ah, ab + (unsigned)(mb * 16 * PITCH + ks * 32));
                    #pragma unroll
                    for (int jj = 0; jj < 4; jj++) {
                        mma16816(acc[mb][jj * 2],     ah, bh[jj]);      // n8 tile 2jj
                        mma16816(acc[mb][jj * 2 + 1], ah, bh[jj] + 2);  // n8 tile 2jj+1
                    }
                }
            }
            buf ^= 1;
        }

        // ---- epilogue: bias + relu, streaming stores ----
        #pragma unroll
        for (int mb = 0; mb < 2; mb++) {
            const int r0 = mt * MTILE + wm * 32 + mb * 16 + (l >> 2);
            #pragma unroll
            for (int j = 0; j < 8; j++) {
                int n = wn * 64 + j * 8 + 2 * (l & 3);
                float2 bv = *(const float2*)(beffs + n);
                float* p0 = out + (size_t)r0 * NDIM + ntl * NTILE + n;
                stcs2(p0,
                      fmaxf(acc[mb][j][0] + bv.x, 0.f),
                      fmaxf(acc[mb][j][1] + bv.y, 0.f));
                stcs2(p0 + 8 * NDIM,
                      fmaxf(acc[mb][j][2] + bv.x, 0.f),
                      fmaxf(acc[mb][j][3] + bv.y, 0.f));
            }
        }
        mt += mstride;
    }
}

// ===================== launch =====================
extern "C" void kernel_launch(void* const* d_in, const int* in_sizes, int n_in,
                              void* d_out, int out_size) {
    const float* x  = (const float*)d_in[0];
    const float* Wg = (const float*)d_in[1];
    const float* bg = (const float*)d_in[2];
    const float* Wm = (const float*)d_in[3];
    float* out = (float*)d_out;

    const int B   = in_sizes[0] / KDIM;      // 32768
    const int ntm = B / MTILE;               // 256

    cudaFuncSetAttribute(gemm_kernel,
                         cudaFuncAttributeMaxDynamicSharedMemorySize, SMEM_TOTAL);

    int dev = 0, sms = 148;
    cudaGetDevice(&dev);
    cudaDeviceGetAttribute(&sms, cudaDevAttrMultiProcessorCount, dev);
    int grid = (2 * sms) & ~3;               // 2 CTAs/SM, multiple of 4 (N quarters)
    if (grid < 4) grid = 4;
    if (grid > 4 * ntm) grid = 4 * ntm;
    int mstride = grid >> 2;

    gemm_kernel<<<grid, THREADS, SMEM_TOTAL>>>(x, out, Wg, bg, Wm, ntm, mstride);
}

// round 14
// speedup vs baseline: 1.8799x; 1.6195x over previous
#include <cuda_runtime.h>
#include <cuda_fp16.h>

// ===================== problem constants =====================
#define KDIM    256            // x row: c*64+d
#define NDIM    512            // t*32+o
#define MTILE   32
#define THREADS 512

// ===================== smem layout =====================
#define PITCH   144                        // 64 fp16 (128B) + 16B pad (validated conflict-free)
#define TTOK    (32 * PITCH)               // 4608 per token sub-tile (32 rows)
#define YBUF    (16 * TTOK)                // 73728 per y buffer; Wg staged here at init too
#define SM_Y    0                          // 2 buffers: 147456
#define SM_WMD  (2 * YBUF)                 // dup-packed Wm: 16*4 u64 = 512
#define SMEM_TOTAL (SM_WMD + 512 + 128)    // 148096 (1 CTA/SM)

typedef unsigned long long u64;

// ===================== PTX helpers (validated mappings) =====================
__device__ __forceinline__ unsigned smem_u32(const void* p) {
    unsigned a;
    asm("{ .reg .u64 t; cvta.to.shared.u64 t, %1; cvt.u32.u64 %0, t; }" : "=r"(a) : "l"(p));
    return a;
}
__device__ __forceinline__ u64 ffma2(u64 a, u64 b, u64 c) {
    u64 d;
    asm("fma.rn.f32x2 %0, %1, %2, %3;" : "=l"(d) : "l"(a), "l"(b), "l"(c));
    return d;
}
__device__ __forceinline__ u64 fmul2(u64 a, u64 b) {
    u64 d;
    asm("mul.rn.f32x2 %0, %1, %2;" : "=l"(d) : "l"(a), "l"(b));
    return d;
}
__device__ __forceinline__ float f2lo(u64 v) { return __int_as_float((int)(unsigned)v); }
__device__ __forceinline__ float f2hi(u64 v) { return __int_as_float((int)(unsigned)(v >> 32)); }
__device__ __forceinline__ void ldmx4(unsigned* r, unsigned addr) {
    asm volatile("ldmatrix.sync.aligned.m8n8.x4.shared.b16 {%0,%1,%2,%3}, [%4];"
                 : "=r"(r[0]), "=r"(r[1]), "=r"(r[2]), "=r"(r[3]) : "r"(addr));
}
__device__ __forceinline__ void mma16816(float* d, const unsigned* a, const unsigned* b) {
    asm volatile("mma.sync.aligned.m16n8k16.row.col.f32.f16.f16.f32 "
                 "{%0,%1,%2,%3}, {%4,%5,%6,%7}, {%8,%9}, {%0,%1,%2,%3};"
                 : "+f"(d[0]), "+f"(d[1]), "+f"(d[2]), "+f"(d[3])
                 : "r"(a[0]), "r"(a[1]), "r"(a[2]), "r"(a[3]), "r"(b[0]), "r"(b[1]));
}
__device__ __forceinline__ void stcs2(float* p, float a, float b) {
    asm volatile("st.global.cs.v2.f32 [%0], {%1, %2};" :: "l"(p), "f"(a), "f"(b) : "memory");
}

// ===================== single kernel, two-stage, warp-per-token =====================
__global__ __launch_bounds__(THREADS, 1)
void ftok_kernel(const float* __restrict__ x,   float* __restrict__ out,
                 const float* __restrict__ Wg,  const float* __restrict__ bg,
                 const float* __restrict__ Wm,  int ntiles, int stride) {
    extern __shared__ char smem[];
    const unsigned sb = smem_u32(smem);
    const int tid = threadIdx.x, wid = tid >> 5, l = tid & 31;
    const int t  = wid;                   // warp owns token t (stage2)
    const int m1 = tid >> 4;              // stage1 row (0..31)
    const int dg = tid & 15;              // stage1 d-group (4 d's)
    int mt = blockIdx.x;

    // ---- init A: stage Wg (fp32->fp16) into y-region temporarily, pitch 144 ----
    // 8192 float4: row(512 = t*32+n) x j4(16)
    #pragma unroll
    for (int i = 0; i < 16; i++) {
        int u = tid + i * THREADS;
        int row = u >> 4, j4 = u & 15;
        float4 v = *(const float4*)(Wg + (size_t)row * 64 + j4 * 4);
        __half2 h0 = __float22half2_rn(make_float2(v.x, v.y));
        __half2 h1 = __float22half2_rn(make_float2(v.z, v.w));
        *(uint2*)(smem + SM_Y + row * PITCH + j4 * 8) =
            make_uint2(*(unsigned*)&h0, *(unsigned*)&h1);
    }
    // dup-packed Wm for stage1 f32x2
    if (tid < 64) {
        unsigned w = __float_as_uint(Wm[tid]);
        ((u64*)(smem + SM_WMD))[tid] = ((u64)w << 32) | w;
    }

    // ---- init B: register-resident beff for this warp's 8 output columns ----
    float2 be[4];
    {
        float s = Wm[t * 4] + Wm[t * 4 + 1] + Wm[t * 4 + 2] + Wm[t * 4 + 3];
        #pragma unroll
        for (int j = 0; j < 4; j++) {
            float2 b = *(const float2*)(bg + t * 32 + j * 8 + 2 * (l & 3));
            be[j] = make_float2(s * b.x, s * b.y);
        }
    }

    // ---- prologue LDG: x tile mt into regs ----
    float4 xr[4];
    {
        const float* xrow = x + ((size_t)(mt * MTILE + m1)) * KDIM + dg * 4;
        #pragma unroll
        for (int c = 0; c < 4; c++) xr[c] = *(const float4*)(xrow + c * 64);
    }

    __syncthreads();  // Wg staged & Wm dup visible

    // ---- extract register-resident B fragments (token t), once ----
    unsigned bf[4][8];                    // [ks][2 regs x 4 n8-tiles]
    {
        const unsigned b_lane = sb + SM_Y + (unsigned)(t * TTOK) +
            (unsigned)(((l & 7) + ((l >> 4) & 1) * 8) * PITCH + ((l >> 3) & 1) * 16);
        #pragma unroll
        for (int ks = 0; ks < 4; ks++) {
            ldmx4(&bf[ks][0], b_lane + (unsigned)(ks * 32));                 // n8 tiles 0,1
            ldmx4(&bf[ks][4], b_lane + (unsigned)(16 * PITCH + ks * 32));    // n8 tiles 2,3
        }
    }
    __syncthreads();  // all warps done reading Wg; y-region reusable

    const ulonglong2* wmd = (const ulonglong2*)(smem + SM_WMD);
    const unsigned ysts = (unsigned)(m1 * PITCH + dg * 8);
    const unsigned a_lane = sb + SM_Y + (unsigned)(t * TTOK) +
        (unsigned)((l & 15) * PITCH + (l >> 4) * 16);

    // ---- stage1: y[m1][*][dg*4..+3] for all 16 tokens -> buffer b (fp16) ----
    auto stage1 = [&](int b) {
        const u64* xp = (const u64*)xr;       // xp[2c], xp[2c+1] = d pairs
        #pragma unroll
        for (int tt = 0; tt < 16; tt++) {
            ulonglong2 m01 = wmd[tt * 2], m23 = wmd[tt * 2 + 1];
            u64 a0 = fmul2(m01.x, xp[0]);
            u64 a1 = fmul2(m01.x, xp[1]);
            a0 = ffma2(m01.y, xp[2], a0);  a1 = ffma2(m01.y, xp[3], a1);
            a0 = ffma2(m23.x, xp[4], a0);  a1 = ffma2(m23.x, xp[5], a1);
            a0 = ffma2(m23.y, xp[6], a0);  a1 = ffma2(m23.y, xp[7], a1);
            __half2 h0 = __float22half2_rn(make_float2(f2lo(a0), f2hi(a0)));
            __half2 h1 = __float22half2_rn(make_float2(f2lo(a1), f2hi(a1)));
            *(uint2*)(smem + SM_Y + b * YBUF + tt * TTOK + ysts) =
                make_uint2(*(unsigned*)&h0, *(unsigned*)&h1);
        }
    };

    stage1(0);
    // prefetch x tile mt+stride
    {
        int nmt = mt + stride;
        if (nmt < ntiles) {
            const float* xrow = x + ((size_t)(nmt * MTILE + m1)) * KDIM + dg * 4;
            #pragma unroll
            for (int c = 0; c < 4; c++) xr[c] = *(const float4*)(xrow + c * 64);
        }
    }
    __syncthreads();  // y[0] ready

    int buf = 0;
    for (; mt < ntiles; mt += stride) {
        // ---- stage2: token t, [32m x 32n, K=64], B in registers ----
        float acc[2][4][4];
        #pragma unroll
        for (int mg = 0; mg < 2; mg++)
            #pragma unroll
            for (int j = 0; j < 4; j++)
                #pragma unroll
                for (int q = 0; q < 4; q++) acc[mg][j][q] = 0.f;

        const unsigned ab = a_lane + (unsigned)(buf * YBUF);
        #pragma unroll
        for (int mg = 0; mg < 2; mg++) {
            #pragma unroll
            for (int ks = 0; ks < 4; ks++) {
                unsigned ah[4];
                ldmx4(ah, ab + (unsigned)(mg * 16 * PITCH + ks * 32));
                #pragma unroll
                for (int j = 0; j < 4; j++)
                    mma16816(acc[mg][j], ah, &bf[ks][2 * j]);
            }
        }

        // ---- epilogue: bias + relu, streaming stores ----
        #pragma unroll
        for (int mg = 0; mg < 2; mg++) {
            const int r0 = mt * MTILE + mg * 16 + (l >> 2);
            #pragma unroll
            for (int j = 0; j < 4; j++) {
                int col = t * 32 + j * 8 + 2 * (l & 3);
                float* p0 = out + (size_t)r0 * NDIM + col;
                stcs2(p0,
                      fmaxf(acc[mg][j][0] + be[j].x, 0.f),
                      fmaxf(acc[mg][j][1] + be[j].y, 0.f));
                stcs2(p0 + 8 * NDIM,
                      fmaxf(acc[mg][j][2] + be[j].x, 0.f),
                      fmaxf(acc[mg][j][3] + be[j].y, 0.f));
            }
        }

        // ---- stage1 for tile mt+stride into other buffer; prefetch mt+2*stride ----
        {
            int nmt = mt + stride;
            if (nmt < ntiles) {
                stage1(buf ^ 1);
                int pmt = nmt + stride;
                if (pmt < ntiles) {
                    const float* xrow = x + ((size_t)(pmt * MTILE + m1)) * KDIM + dg * 4;
                    #pragma unroll
                    for (int c = 0; c < 4; c++) xr[c] = *(const float4*)(xrow + c * 64);
                }
            }
        }

        __syncthreads();  // y[buf^1] ready; y[buf] free for reuse
        buf ^= 1;
    }
}

// ===================== launch =====================
extern "C" void kernel_launch(void* const* d_in, const int* in_sizes, int n_in,
                              void* d_out, int out_size) {
    const float* x  = (const float*)d_in[0];
    const float* Wg = (const float*)d_in[1];
    const float* bg = (const float*)d_in[2];
    const float* Wm = (const float*)d_in[3];
    float* out = (float*)d_out;

    const int B      = in_sizes[0] / KDIM;   // 32768
    const int ntiles = B / MTILE;            // 1024

    cudaFuncSetAttribute(ftok_kernel,
                         cudaFuncAttributeMaxDynamicSharedMemorySize, SMEM_TOTAL);

    int dev = 0, sms = 148;
    cudaGetDevice(&dev);
    cudaDeviceGetAttribute(&sms, cudaDevAttrMultiProcessorCount, dev);
    int grid = sms < ntiles ? sms : ntiles;

    ftok_kernel<<<grid, THREADS, SMEM_TOTAL>>>(x, out, Wg, bg, Wm, ntiles, grid);
}